// round 5
// baseline (speedup 1.0000x reference)
#include <cuda_runtime.h>

// Ball query (radius=2, nsample=32) + gather(xyz/2, feat) + concat.
// One 256-thread block per query, 3-phase adaptive scan:
//   phase 0: points [0,256), 1 pt/thread           (median query stops here)
//   phase 1: points [256,1280), 4 pts/thread       (~98% stop here)
//   phase 2: points [1280,N) in ONE barrier-free pass, 60 pts/thread,
//            64-bit hit masks + single block prefix compaction (straggler fix)

#define KNN 32
#define THREADS 256
#define NWARP (THREADS / 32)   // 8

__device__ __forceinline__ float dist2(float qq, float qx, float qy, float qz,
                                       float px, float py, float pz) {
    // reference's algebraic form: |q|^2 - 2 q.x + |x|^2
    return qq - 2.0f * (qx * px + qy * py + qz * pz) + (px * px + py * py + pz * pz);
}

// Ordered compaction of this chunk's hits into s_idx (small-mask version).
__device__ __forceinline__ int compact_write(
    unsigned ok_bits, int base_ptidx,
    int warp, int lane, int buf,
    unsigned s_wcnt[3][NWARP], int* s_idx, int count)
{
    const int c = __popc(ok_bits);
    int inc = c;
    #pragma unroll
    for (int off = 1; off < 32; off <<= 1) {
        const int v = __shfl_up_sync(0xffffffffu, inc, off);
        if (lane >= off) inc += v;
    }
    if (lane == 31) s_wcnt[buf][warp] = (unsigned)inc;
    __syncthreads();

    int wbase = 0, total = 0;
    #pragma unroll
    for (int w = 0; w < NWARP; ++w) {
        const int t = (int)s_wcnt[buf][w];
        if (w < warp) wbase += t;
        total += t;
    }
    int slot = count + wbase + (inc - c);
    unsigned bits = ok_bits;
    while (bits && slot < KNN) {
        const int j = __ffs(bits) - 1;
        bits &= bits - 1;
        s_idx[slot++] = base_ptidx + j;
    }
    return count + total;
}

__global__ __launch_bounds__(THREADS)
void ball_query_gather_kernel(
    const float* __restrict__ q_xyz,   // (Q, 3)
    const float* __restrict__ pts,     // (B, N, 3)
    const float* __restrict__ feat,    // (B, N, 32)
    float* __restrict__ out,           // (Q, KNN, 35)
    int Q, int N, int Qper)
{
    const int q    = blockIdx.x;
    const int tid  = threadIdx.x;
    const int warp = tid >> 5;
    const int lane = tid & 31;

    __shared__ int      s_idx[KNN];
    __shared__ unsigned s_wcnt[3][NWARP];

    const int b = q / Qper;
    const float* __restrict__ p = pts  + (size_t)b * N * 3;
    const float* __restrict__ f = feat + (size_t)b * N * 32;

    const float qx = q_xyz[q * 3 + 0];
    const float qy = q_xyz[q * 3 + 1];
    const float qz = q_xyz[q * 3 + 2];
    const float qq = qx * qx + qy * qy + qz * qz;

    // --- phase 0: points [0, 256), 1 point per thread ---
    int count;
    {
        const int n = tid;
        const float d2 = dist2(qq, qx, qy, qz, p[n*3+0], p[n*3+1], p[n*3+2]);
        count = compact_write(d2 <= 4.0f ? 1u : 0u, n, warp, lane, 0,
                              s_wcnt, s_idx, 0);
    }

    // --- phase 1: points [256, 1280), 4 points per thread (3x float4) ---
    if (count < KNN) {
        const int base4 = THREADS + 4 * tid;
        const float4* pv = reinterpret_cast<const float4*>(p + (size_t)base4 * 3);
        const float4 v0 = pv[0], v1 = pv[1], v2 = pv[2];
        const float d0 = dist2(qq,qx,qy,qz, v0.x,v0.y,v0.z);
        const float d1 = dist2(qq,qx,qy,qz, v0.w,v1.x,v1.y);
        const float d2_ = dist2(qq,qx,qy,qz, v1.z,v1.w,v2.x);
        const float d3 = dist2(qq,qx,qy,qz, v2.y,v2.z,v2.w);
        const unsigned bits = (d0 <= 4.0f ? 1u : 0u) | (d1 <= 4.0f ? 2u : 0u)
                            | (d2_ <= 4.0f ? 4u : 0u) | (d3 <= 4.0f ? 8u : 0u);
        count = compact_write(bits, base4, warp, lane, 1, s_wcnt, s_idx, count);
    }

    // --- phase 2: points [1280, N) in one barrier-free pass, 60 pts/thread ---
    if (count < KNN) {
        const int tstart = 5 * THREADS + 60 * tid;   // 1280 + 60*tid
        unsigned long long mask = 0ull;
        if (tstart + 60 <= N) {
            // fast path: fully in range, float4-aligned (720B contiguous)
            #pragma unroll 5
            for (int i = 0; i < 15; ++i) {
                const float4* pv = reinterpret_cast<const float4*>(
                    p + (size_t)(tstart + 4 * i) * 3);
                const float4 v0 = pv[0], v1 = pv[1], v2 = pv[2];
                const float d0 = dist2(qq,qx,qy,qz, v0.x,v0.y,v0.z);
                const float d1 = dist2(qq,qx,qy,qz, v0.w,v1.x,v1.y);
                const float d2_ = dist2(qq,qx,qy,qz, v1.z,v1.w,v2.x);
                const float d3 = dist2(qq,qx,qy,qz, v2.y,v2.z,v2.w);
                const unsigned g = (d0 <= 4.0f ? 1u : 0u) | (d1 <= 4.0f ? 2u : 0u)
                                 | (d2_ <= 4.0f ? 4u : 0u) | (d3 <= 4.0f ? 8u : 0u);
                mask |= (unsigned long long)g << (4 * i);
            }
        } else {
            for (int j = 0; j < 60; ++j) {
                const int n = tstart + j;
                if (n < N) {
                    const float d2 = dist2(qq,qx,qy,qz,
                                           p[n*3+0], p[n*3+1], p[n*3+2]);
                    if (d2 <= 4.0f) mask |= 1ull << j;
                }
            }
        }

        // single block compaction of the 64-bit masks (index order preserved)
        const int c = __popcll(mask);
        int inc = c;
        #pragma unroll
        for (int off = 1; off < 32; off <<= 1) {
            const int v = __shfl_up_sync(0xffffffffu, inc, off);
            if (lane >= off) inc += v;
        }
        if (lane == 31) s_wcnt[2][warp] = (unsigned)inc;
        __syncthreads();

        int wbase = 0, total = 0;
        #pragma unroll
        for (int w = 0; w < NWARP; ++w) {
            const int t = (int)s_wcnt[2][w];
            if (w < warp) wbase += t;
            total += t;
        }
        int slot = count + wbase + (inc - c);
        unsigned long long bits = mask;
        while (bits && slot < KNN) {
            const int j = __ffsll(bits) - 1;
            bits &= bits - 1ull;
            s_idx[slot++] = tstart + j;
        }
        count += total;
    }
    __syncthreads();   // publish s_idx

    // --- degenerate fill ---
    if (count < KNN) {
        const int first = (count > 0) ? s_idx[0] : (N - 1);  // JAX clamps OOB gather
        if (tid >= count && tid < KNN) s_idx[tid] = first;
        __syncthreads();
    }

    // --- gather + concat: 8 warps x 4 independent neighbor rows, coalesced ---
    float* __restrict__ o = out + (size_t)q * KNN * 35;
    int kidx[KNN / NWARP];
    #pragma unroll
    for (int i = 0; i < KNN / NWARP; ++i)
        kidx[i] = s_idx[warp * (KNN / NWARP) + i];
    #pragma unroll
    for (int i = 0; i < KNN / NWARP; ++i) {
        const int k   = warp * (KNN / NWARP) + i;
        const int idx = kidx[i];
        o[k * 35 + 3 + lane] = f[idx * 32 + lane];        // 128B coalesced
        if (lane < 3)
            o[k * 35 + lane] = p[idx * 3 + lane] * 0.5f;  // nn_xyz / D_RADIUS
    }
}

extern "C" void kernel_launch(void* const* d_in, const int* in_sizes, int n_in,
                              void* d_out, int out_size) {
    const float* candidate_pts = (const float*)d_in[0];  // (B,128,10,3)
    const float* tgt_pts_xyz   = (const float*)d_in[2];  // (B,N,3)
    const float* tgt_feat      = (const float*)d_in[3];  // (B,N,32)
    float* out = (float*)d_out;

    const int B = 2;
    const int Q = in_sizes[0] / 3;           // 2560
    const int N = in_sizes[2] / (3 * B);     // 16384
    const int Qper = Q / B;                  // 1280

    ball_query_gather_kernel<<<Q, THREADS>>>(
        candidate_pts, tgt_pts_xyz, tgt_feat, out, Q, N, Qper);
}

// round 6
// speedup vs baseline: 1.4168x; 1.4168x over previous
#include <cuda_runtime.h>

// Ball query (radius=2, nsample=32) + gather(xyz/2, feat) + concat.
// One 256-thread block per query; geometric 4-phase adaptive scan:
//   phase 0: [0,256)      1 pt/thread    (median query stops here)
//   phase 1: [256,1280)   4 pts/thread   (~98% stop here)
//   phase 2: [1280,5376)  16 pts/thread
//   phase 3: [5376,N)     44 pts/thread  (rare extreme stragglers)
// Ordered block compaction per phase: warp shfl scan + parity-buffered
// per-warp totals (one barrier per phase). Registers capped via launch
// bounds so deep phases cannot hurt common-case occupancy.

#define KNN 32
#define THREADS 256
#define NWARP (THREADS / 32)   // 8

__device__ __forceinline__ float dist2(float qq, float qx, float qy, float qz,
                                       float px, float py, float pz) {
    // reference's algebraic form: |q|^2 - 2 q.x + |x|^2
    return qq - 2.0f * (qx * px + qy * py + qz * pz) + (px * px + py * py + pz * pz);
}

// Ordered compaction of this phase's hits into s_idx. Bit j of ok_bits set
// means point (base_ptidx + j) is in radius. Returns updated block count.
__device__ __forceinline__ int compact_write(
    unsigned long long ok_bits, int base_ptidx,
    int warp, int lane, int buf,
    volatile unsigned s_wcnt[2][NWARP], int* s_idx, int count)
{
    const int c = __popcll(ok_bits);
    int inc = c;
    #pragma unroll
    for (int off = 1; off < 32; off <<= 1) {
        const int v = __shfl_up_sync(0xffffffffu, inc, off);
        if (lane >= off) inc += v;
    }
    if (lane == 31) s_wcnt[buf][warp] = (unsigned)inc;
    __syncthreads();                               // only barrier per phase

    int wbase = 0, total = 0;
    #pragma unroll
    for (int w = 0; w < NWARP; ++w) {
        const int t = (int)s_wcnt[buf][w];
        if (w < warp) wbase += t;
        total += t;
    }
    int slot = count + wbase + (inc - c);
    unsigned long long bits = ok_bits;
    while (bits && slot < KNN) {
        const int j = __ffsll(bits) - 1;
        bits &= bits - 1ull;
        s_idx[slot++] = base_ptidx + j;
    }
    return count + total;
}

// Distance-test 4 consecutive points starting at float4-aligned index b4.
__device__ __forceinline__ unsigned test4(const float* __restrict__ p, int b4,
                                          float qq, float qx, float qy, float qz)
{
    const float4* pv = reinterpret_cast<const float4*>(p + (size_t)b4 * 3);
    const float4 v0 = pv[0], v1 = pv[1], v2 = pv[2];
    const float d0 = dist2(qq, qx, qy, qz, v0.x, v0.y, v0.z);
    const float d1 = dist2(qq, qx, qy, qz, v0.w, v1.x, v1.y);
    const float d2 = dist2(qq, qx, qy, qz, v1.z, v1.w, v2.x);
    const float d3 = dist2(qq, qx, qy, qz, v2.y, v2.z, v2.w);
    return (d0 <= 4.0f ? 1u : 0u) | (d1 <= 4.0f ? 2u : 0u)
         | (d2 <= 4.0f ? 4u : 0u) | (d3 <= 4.0f ? 8u : 0u);
}

__global__ __launch_bounds__(THREADS, 7)   // cap regs ~36: protect occupancy
void ball_query_gather_kernel(
    const float* __restrict__ q_xyz,   // (Q, 3)
    const float* __restrict__ pts,     // (B, N, 3)
    const float* __restrict__ feat,    // (B, N, 32)
    float* __restrict__ out,           // (Q, KNN, 35)
    int Q, int N, int Qper)
{
    const int q    = blockIdx.x;
    const int tid  = threadIdx.x;
    const int warp = tid >> 5;
    const int lane = tid & 31;

    __shared__ int      s_idx[KNN];
    __shared__ unsigned s_wcnt[2][NWARP];

    const int b = q / Qper;
    const float* __restrict__ p = pts  + (size_t)b * N * 3;
    const float* __restrict__ f = feat + (size_t)b * N * 32;

    const float qx = q_xyz[q * 3 + 0];
    const float qy = q_xyz[q * 3 + 1];
    const float qz = q_xyz[q * 3 + 2];
    const float qq = qx * qx + qy * qy + qz * qz;

    // --- phase 0: [0,256), 1 point per thread ---
    int count;
    {
        const int n = tid;
        const float d2 = dist2(qq, qx, qy, qz, p[n*3+0], p[n*3+1], p[n*3+2]);
        count = compact_write(d2 <= 4.0f ? 1ull : 0ull, n, warp, lane, 0,
                              s_wcnt, s_idx, 0);
    }

    // --- phase 1: [256,1280), 4 points per thread ---
    if (count < KNN) {
        const int base4 = THREADS + 4 * tid;
        unsigned bits = 0;
        if (base4 + 4 <= N) bits = test4(p, base4, qq, qx, qy, qz);
        count = compact_write(bits, base4, warp, lane, 1, s_wcnt, s_idx, count);
    }

    // --- phase 2: [1280,5376), 16 points per thread ---
    if (count < KNN) {
        const int tstart = 1280 + 16 * tid;
        unsigned long long mask = 0ull;
        #pragma unroll 2
        for (int i = 0; i < 4; ++i) {
            const int b4 = tstart + 4 * i;
            if (b4 + 4 <= N)
                mask |= (unsigned long long)test4(p, b4, qq, qx, qy, qz) << (4 * i);
        }
        count = compact_write(mask, tstart, warp, lane, 0, s_wcnt, s_idx, count);
    }

    // --- phase 3: [5376,N), 44 points per thread (rare) ---
    if (count < KNN) {
        const int tstart = 5376 + 44 * tid;
        unsigned long long mask = 0ull;
        #pragma unroll 2
        for (int i = 0; i < 11; ++i) {
            const int b4 = tstart + 4 * i;
            if (b4 + 4 <= N) {
                mask |= (unsigned long long)test4(p, b4, qq, qx, qy, qz) << (4 * i);
            } else {
                for (int j = 0; j < 4; ++j) {
                    const int n = b4 + j;
                    if (n < N) {
                        const float d2 = dist2(qq, qx, qy, qz,
                                               p[n*3+0], p[n*3+1], p[n*3+2]);
                        if (d2 <= 4.0f) mask |= 1ull << (4 * i + j);
                    }
                }
            }
        }
        count = compact_write(mask, tstart, warp, lane, 1, s_wcnt, s_idx, count);
    }
    __syncthreads();   // publish s_idx

    // --- degenerate fill ---
    if (count < KNN) {
        const int first = (count > 0) ? s_idx[0] : (N - 1);  // JAX clamps OOB gather
        if (tid >= count && tid < KNN) s_idx[tid] = first;
        __syncthreads();
    }

    // --- gather + concat: 8 warps x 4 independent neighbor rows, coalesced ---
    float* __restrict__ o = out + (size_t)q * KNN * 35;
    int kidx[KNN / NWARP];
    #pragma unroll
    for (int i = 0; i < KNN / NWARP; ++i)
        kidx[i] = s_idx[warp * (KNN / NWARP) + i];
    #pragma unroll
    for (int i = 0; i < KNN / NWARP; ++i) {
        const int k   = warp * (KNN / NWARP) + i;
        const int idx = kidx[i];
        o[k * 35 + 3 + lane] = f[idx * 32 + lane];        // 128B coalesced
        if (lane < 3)
            o[k * 35 + lane] = p[idx * 3 + lane] * 0.5f;  // nn_xyz / D_RADIUS
    }
}

extern "C" void kernel_launch(void* const* d_in, const int* in_sizes, int n_in,
                              void* d_out, int out_size) {
    const float* candidate_pts = (const float*)d_in[0];  // (B,128,10,3)
    const float* tgt_pts_xyz   = (const float*)d_in[2];  // (B,N,3)
    const float* tgt_feat      = (const float*)d_in[3];  // (B,N,32)
    float* out = (float*)d_out;

    const int B = 2;
    const int Q = in_sizes[0] / 3;           // 2560
    const int N = in_sizes[2] / (3 * B);     // 16384
    const int Qper = Q / B;                  // 1280

    ball_query_gather_kernel<<<Q, THREADS>>>(
        candidate_pts, tgt_pts_xyz, tgt_feat, out, Q, N, Qper);
}